// round 6
// baseline (speedup 1.0000x reference)
#include <cuda_runtime.h>
#include <math.h>

// Router: logits = x @ W^T ; softmax ; top-8 ; scatter gates + one-hot map.
// x: [T, 2048] fp32, W: [64, 2048] fp32
// out: [2*T*64] fp32 : first T*64 = dense top-k gates, next T*64 = one-hot map (0/1)
//
// R4: (a) logits accumulated in fp64 (exact at the 1e-11 level), rounded to fp32
//     before the epilogue — removes my GEMM-rounding contribution to top-8
//     boundary decisions. (b) ranking done on the NORMALIZED fp32 quotient
//     q = fl(p/s) with FTZ (q < FLT_MIN -> 0), replicating the reference's
//     softmax-then-top_k tie semantics including the division flush band.

#define HID   2048
#define NEXP  64
#define TOPK  8
#define BM    64          // rows per block
#define BK    32          // K tile
#define NTHREADS 256
#define FLT_MIN_POS 1.17549435e-38f

__global__ __launch_bounds__(NTHREADS, 2)
void router_kernel(const float* __restrict__ x,
                   const float* __restrict__ w,
                   float* __restrict__ out,
                   int T)
{
    // K-transposed tiles: [k][row] so inner loop reads contiguous float4
    __shared__ float xs[BK][BM + 4];
    __shared__ float ws[BK][NEXP + 4];
    __shared__ float logits[BM][NEXP + 1];

    const int tid = threadIdx.x;
    const int tx = tid & 15;   // expert group: experts tx*4 .. tx*4+3
    const int ty = tid >> 4;   // row group:    rows    ty*4 .. ty*4+3
    const int rowBase = blockIdx.x * BM;

    double acc[4][4];
#pragma unroll
    for (int i = 0; i < 4; i++)
#pragma unroll
        for (int j = 0; j < 4; j++) acc[i][j] = 0.0;

    // Tile is 64 rows x 32 floats = 512 float4; each thread loads f and f+256.
    const int f0 = tid, f1 = tid + NTHREADS;
    const int r0 = f0 >> 3, q0 = f0 & 7;     // row-in-tile, float4-in-row
    const int r1 = f1 >> 3, q1 = f1 & 7;

    const float4* __restrict__ xg = (const float4*)x;  // row stride 512 float4
    const float4* __restrict__ wg = (const float4*)w;

    float4 xreg0, xreg1, wreg0, wreg1;
    xreg0 = xg[(size_t)(rowBase + r0) * (HID / 4) + q0];
    xreg1 = xg[(size_t)(rowBase + r1) * (HID / 4) + q1];
    wreg0 = wg[(size_t)r0 * (HID / 4) + q0];
    wreg1 = wg[(size_t)r1 * (HID / 4) + q1];

    const int NT = HID / BK;   // 64 K-tiles
    for (int t = 0; t < NT; t++) {
        // regs -> smem (transposed)
        {
            float4 v = xreg0;
            xs[q0 * 4 + 0][r0] = v.x; xs[q0 * 4 + 1][r0] = v.y;
            xs[q0 * 4 + 2][r0] = v.z; xs[q0 * 4 + 3][r0] = v.w;
            v = xreg1;
            xs[q1 * 4 + 0][r1] = v.x; xs[q1 * 4 + 1][r1] = v.y;
            xs[q1 * 4 + 2][r1] = v.z; xs[q1 * 4 + 3][r1] = v.w;
            v = wreg0;
            ws[q0 * 4 + 0][r0] = v.x; ws[q0 * 4 + 1][r0] = v.y;
            ws[q0 * 4 + 2][r0] = v.z; ws[q0 * 4 + 3][r0] = v.w;
            v = wreg1;
            ws[q1 * 4 + 0][r1] = v.x; ws[q1 * 4 + 1][r1] = v.y;
            ws[q1 * 4 + 2][r1] = v.z; ws[q1 * 4 + 3][r1] = v.w;
        }
        __syncthreads();

        // prefetch next K-tile into registers (overlaps with compute below)
        if (t + 1 < NT) {
            const int ko = (t + 1) * (BK / 4);
            xreg0 = xg[(size_t)(rowBase + r0) * (HID / 4) + ko + q0];
            xreg1 = xg[(size_t)(rowBase + r1) * (HID / 4) + ko + q1];
            wreg0 = wg[(size_t)r0 * (HID / 4) + ko + q0];
            wreg1 = wg[(size_t)r1 * (HID / 4) + ko + q1];
        }

#pragma unroll
        for (int kk = 0; kk < BK; kk++) {
            float4 xv = *(const float4*)&xs[kk][ty * 4];
            float4 wv = *(const float4*)&ws[kk][tx * 4];
            double xd0 = (double)xv.x, xd1 = (double)xv.y,
                   xd2 = (double)xv.z, xd3 = (double)xv.w;
            double wd0 = (double)wv.x, wd1 = (double)wv.y,
                   wd2 = (double)wv.z, wd3 = (double)wv.w;
            acc[0][0] = fma(xd0, wd0, acc[0][0]);
            acc[0][1] = fma(xd0, wd1, acc[0][1]);
            acc[0][2] = fma(xd0, wd2, acc[0][2]);
            acc[0][3] = fma(xd0, wd3, acc[0][3]);
            acc[1][0] = fma(xd1, wd0, acc[1][0]);
            acc[1][1] = fma(xd1, wd1, acc[1][1]);
            acc[1][2] = fma(xd1, wd2, acc[1][2]);
            acc[1][3] = fma(xd1, wd3, acc[1][3]);
            acc[2][0] = fma(xd2, wd0, acc[2][0]);
            acc[2][1] = fma(xd2, wd1, acc[2][1]);
            acc[2][2] = fma(xd2, wd2, acc[2][2]);
            acc[2][3] = fma(xd2, wd3, acc[2][3]);
            acc[3][0] = fma(xd3, wd0, acc[3][0]);
            acc[3][1] = fma(xd3, wd1, acc[3][1]);
            acc[3][2] = fma(xd3, wd2, acc[3][2]);
            acc[3][3] = fma(xd3, wd3, acc[3][3]);
        }
        __syncthreads();
    }

    // dump logits to smem, rounded to fp32 (the reference's logits are fp32)
#pragma unroll
    for (int i = 0; i < 4; i++)
#pragma unroll
        for (int j = 0; j < 4; j++)
            logits[ty * 4 + i][tx * 4 + j] = (float)acc[i][j];
    __syncthreads();

    // Epilogue: one thread per row — softmax + top-8 + scatter
    if (tid < BM) {
        const int row = rowBase + tid;

        float m = -1e30f;
#pragma unroll
        for (int e = 0; e < NEXP; e++) m = fmaxf(m, logits[tid][e]);

        float s = 0.0f;
#pragma unroll
        for (int e = 0; e < NEXP; e++) {
            float p = expf(logits[tid][e] - m);
            // FTZ semantics of the reference's exp: sub-FLT_MIN results form
            // one tied floor group (R2->R3 evidence: 0.178 -> 0.0039).
            if (p < FLT_MIN_POS) p = 0.0f;
            logits[tid][e] = p;
            s += p;
        }

        // Rank by the NORMALIZED fp32 quotient with FTZ, exactly as the
        // reference does (softmax divides, THEN top_k). The division extends
        // the tie group to p < s*FLT_MIN — a band of width ln(s) that the
        // unnormalized ranking misses on rows with a close top-2.
#pragma unroll
        for (int e = 0; e < NEXP; e++) {
            float q = __fdiv_rn(logits[tid][e], s);
            if (q < FLT_MIN_POS) q = 0.0f;
            logits[tid][e] = q;
        }

        // top-8 by probs; strict '>' scan => first index wins ties (matches lax.top_k)
        unsigned long long mask = 0ull;
        for (int k = 0; k < TOPK; k++) {
            float bv = -1.0f;
            int   bi = 0;
            for (int e = 0; e < NEXP; e++) {
                float v = logits[tid][e];
                if (!((mask >> e) & 1ull) && v > bv) { bv = v; bi = e; }
            }
            mask |= (1ull << bi);
        }

        float* __restrict__ gout = out + (size_t)row * NEXP;
        float* __restrict__ mout = out + (size_t)T * NEXP + (size_t)row * NEXP;
#pragma unroll
        for (int e = 0; e < NEXP; e++) {
            const bool sel = (mask >> e) & 1ull;
            gout[e] = sel ? logits[tid][e] : 0.0f;
            mout[e] = sel ? 1.0f : 0.0f;
        }
    }
}

extern "C" void kernel_launch(void* const* d_in, const int* in_sizes, int n_in,
                              void* d_out, int out_size)
{
    const float* x = (const float*)d_in[0];
    const float* w = (const float*)d_in[1];
    float* out = (float*)d_out;
    const int T = in_sizes[0] / HID;       // 16384
    const int grid = T / BM;               // 256
    router_kernel<<<grid, NTHREADS>>>(x, w, out, T);
}

// round 9
// speedup vs baseline: 9.2074x; 9.2074x over previous
#include <cuda_runtime.h>
#include <math.h>

// Router: logits = x @ W^T ; softmax ; top-8 ; scatter gates + one-hot map.
// x: [T, 2048] fp32, W: [64, 2048] fp32
// out: [2*T*64] fp32 : first T*64 = dense gates, next T*64 = one-hot map
//
// R7: fast fp32 FFMA GEMM + per-row robustness guard. Rows whose top-8
// boundary margin < GUARD are recomputed exactly in fp64 by the whole block
// and re-decided with the R6-validated epilogue (which passed end-to-end).

#define HID   2048
#define NEXP  64
#define TOPK  8
#define BM    64
#define BK    32
#define NTHREADS 256
#define FLT_MIN_POS 1.17549435e-38f
#define EXP_CUT     87.336544f
#define GUARD       0.05f
#define GUARD_CUT   0.02f

__global__ __launch_bounds__(NTHREADS, 2)
void router_kernel(const float* __restrict__ x,
                   const float* __restrict__ w,
                   float* __restrict__ out,
                   int T)
{
    __shared__ float xs[BK][BM + 4];
    __shared__ float ws[BK][NEXP + 4];
    __shared__ float lg[BM][NEXP + 1];      // logits, then d = l - m
    __shared__ float qv[BM][NEXP + 1];      // p, then q = p/s (flushed)
    __shared__ int   flagCnt;
    __shared__ int   flagRows[BM];
    __shared__ double red[4][NEXP];
    __shared__ float  exlog[NEXP];

    const int tid = threadIdx.x;
    const int tx = tid & 15;
    const int ty = tid >> 4;
    const int rowBase = blockIdx.x * BM;

    if (tid == 0) flagCnt = 0;

    float acc[4][4];
#pragma unroll
    for (int i = 0; i < 4; i++)
#pragma unroll
        for (int j = 0; j < 4; j++) acc[i][j] = 0.0f;

    const int f0 = tid, f1 = tid + NTHREADS;
    const int r0 = f0 >> 3, q0 = f0 & 7;
    const int r1 = f1 >> 3, q1 = f1 & 7;

    const float4* __restrict__ xg = (const float4*)x;   // row stride 512
    const float4* __restrict__ wg = (const float4*)w;

    float4 xreg0 = xg[(size_t)(rowBase + r0) * (HID / 4) + q0];
    float4 xreg1 = xg[(size_t)(rowBase + r1) * (HID / 4) + q1];
    float4 wreg0 = wg[(size_t)r0 * (HID / 4) + q0];
    float4 wreg1 = wg[(size_t)r1 * (HID / 4) + q1];

    const int NT = HID / BK;
    for (int t = 0; t < NT; t++) {
        {
            float4 v = xreg0;
            xs[q0 * 4 + 0][r0] = v.x; xs[q0 * 4 + 1][r0] = v.y;
            xs[q0 * 4 + 2][r0] = v.z; xs[q0 * 4 + 3][r0] = v.w;
            v = xreg1;
            xs[q1 * 4 + 0][r1] = v.x; xs[q1 * 4 + 1][r1] = v.y;
            xs[q1 * 4 + 2][r1] = v.z; xs[q1 * 4 + 3][r1] = v.w;
            v = wreg0;
            ws[q0 * 4 + 0][r0] = v.x; ws[q0 * 4 + 1][r0] = v.y;
            ws[q0 * 4 + 2][r0] = v.z; ws[q0 * 4 + 3][r0] = v.w;
            v = wreg1;
            ws[q1 * 4 + 0][r1] = v.x; ws[q1 * 4 + 1][r1] = v.y;
            ws[q1 * 4 + 2][r1] = v.z; ws[q1 * 4 + 3][r1] = v.w;
        }
        __syncthreads();

        if (t + 1 < NT) {
            const int ko = (t + 1) * (BK / 4);
            xreg0 = xg[(size_t)(rowBase + r0) * (HID / 4) + ko + q0];
            xreg1 = xg[(size_t)(rowBase + r1) * (HID / 4) + ko + q1];
            wreg0 = wg[(size_t)r0 * (HID / 4) + ko + q0];
            wreg1 = wg[(size_t)r1 * (HID / 4) + ko + q1];
        }

#pragma unroll
        for (int kk = 0; kk < BK; kk++) {
            float4 xv = *(const float4*)&xs[kk][ty * 4];
            float4 wv = *(const float4*)&ws[kk][tx * 4];
            acc[0][0] = fmaf(xv.x, wv.x, acc[0][0]);
            acc[0][1] = fmaf(xv.x, wv.y, acc[0][1]);
            acc[0][2] = fmaf(xv.x, wv.z, acc[0][2]);
            acc[0][3] = fmaf(xv.x, wv.w, acc[0][3]);
            acc[1][0] = fmaf(xv.y, wv.x, acc[1][0]);
            acc[1][1] = fmaf(xv.y, wv.y, acc[1][1]);
            acc[1][2] = fmaf(xv.y, wv.z, acc[1][2]);
            acc[1][3] = fmaf(xv.y, wv.w, acc[1][3]);
            acc[2][0] = fmaf(xv.z, wv.x, acc[2][0]);
            acc[2][1] = fmaf(xv.z, wv.y, acc[2][1]);
            acc[2][2] = fmaf(xv.z, wv.z, acc[2][2]);
            acc[2][3] = fmaf(xv.z, wv.w, acc[2][3]);
            acc[3][0] = fmaf(xv.w, wv.x, acc[3][0]);
            acc[3][1] = fmaf(xv.w, wv.y, acc[3][1]);
            acc[3][2] = fmaf(xv.w, wv.z, acc[3][2]);
            acc[3][3] = fmaf(xv.w, wv.w, acc[3][3]);
        }
        __syncthreads();
    }

#pragma unroll
    for (int i = 0; i < 4; i++)
#pragma unroll
        for (int j = 0; j < 4; j++)
            lg[ty * 4 + i][tx * 4 + j] = acc[i][j];
    __syncthreads();

    // ── Fast epilogue: one thread per row ───────────────────────────────
    if (tid < BM) {
        const int row = rowBase + tid;

        float m = -1e30f;
#pragma unroll
        for (int e = 0; e < NEXP; e++) m = fmaxf(m, lg[tid][e]);

        float s = 0.0f;
#pragma unroll
        for (int e = 0; e < NEXP; e++) {
            float d = lg[tid][e] - m;
            lg[tid][e] = d;                      // keep d for guard checks
            float p = expf(d);
            if (p < FLT_MIN_POS) p = 0.0f;       // exp flush (R2->R3 evidence)
            qv[tid][e] = p;
            s += p;
        }

#pragma unroll
        for (int e = 0; e < NEXP; e++) {
            float q = __fdiv_rn(qv[tid][e], s);
            if (q < FLT_MIN_POS) q = 0.0f;       // division flush band
            qv[tid][e] = q;
        }

        // top-8 by q; strict '>' => first index wins ties (matches lax.top_k)
        unsigned long long mask = 0ull;
        for (int k = 0; k < TOPK; k++) {
            float bv = -1.0f; int bi = 0;
            for (int e = 0; e < NEXP; e++) {
                float v = qv[tid][e];
                if (!((mask >> e) & 1ull) && v > bv) { bv = v; bi = e; }
            }
            mask |= (1ull << bi);
        }

        // ── Robustness guard ────────────────────────────────────────────
        int nA = 0;
        float d8 = 1e30f, d9 = -1e30f;
#pragma unroll
        for (int e = 0; e < NEXP; e++) {
            bool pos = qv[tid][e] > 0.0f;
            bool sel = (mask >> e) & 1ull;
            if (pos) {
                nA++;
                if (sel)  d8 = fminf(d8, lg[tid][e]);
                else      d9 = fmaxf(d9, lg[tid][e]);
            }
        }
        bool flag = false;
        if (d9 > -1e29f && (d8 - d9) < GUARD) flag = true;   // boundary gap
        if (nA <= 8) {                                        // floor-membership edge
            float c = logf(s) - EXP_CUT;
#pragma unroll
            for (int e = 0; e < NEXP; e++)
                if (fabsf(lg[tid][e] - c) < GUARD_CUT) flag = true;
        }

        if (!flag) {
            float* __restrict__ gout = out + (size_t)row * NEXP;
            float* __restrict__ mout = out + (size_t)T * NEXP + (size_t)row * NEXP;
#pragma unroll
            for (int e = 0; e < NEXP; e++) {
                const bool sel = (mask >> e) & 1ull;
                gout[e] = sel ? qv[tid][e] : 0.0f;
                mout[e] = sel ? 1.0f : 0.0f;
            }
        } else {
            flagRows[atomicAdd(&flagCnt, 1)] = tid;
        }
    }
    __syncthreads();

    // ── Exact fp64 repair for flagged rows (whole block per row) ────────
    const int nf = flagCnt;
    for (int r = 0; r < nf; r++) {
        const int lr  = flagRows[r];
        const int row = rowBase + lr;
        const int e   = tid & 63;
        const int ch  = tid >> 6;              // 4 chunks of 512 elements

        const float4* xr = xg + (size_t)row * (HID / 4) + ch * 128;
        const float4* wr = wg + (size_t)e   * (HID / 4) + ch * 128;
        double a0 = 0.0, a1 = 0.0, a2 = 0.0, a3 = 0.0;
#pragma unroll 4
        for (int i = 0; i < 128; i++) {
            float4 xv = xr[i], wv = wr[i];
            a0 = fma((double)xv.x, (double)wv.x, a0);
            a1 = fma((double)xv.y, (double)wv.y, a1);
            a2 = fma((double)xv.z, (double)wv.z, a2);
            a3 = fma((double)xv.w, (double)wv.w, a3);
        }
        red[ch][e] = (a0 + a1) + (a2 + a3);
        __syncthreads();
        if (tid < NEXP)
            exlog[tid] = (float)((red[0][tid] + red[1][tid]) +
                                 (red[2][tid] + red[3][tid]));
        __syncthreads();

        if (tid == 0) {
            // R6-validated epilogue on exact logits
            float m = -1e30f;
            for (int ee = 0; ee < NEXP; ee++) m = fmaxf(m, exlog[ee]);
            float s = 0.0f;
            float pbuf[NEXP];
            for (int ee = 0; ee < NEXP; ee++) {
                float p = expf(exlog[ee] - m);
                if (p < FLT_MIN_POS) p = 0.0f;
                pbuf[ee] = p;
                s += p;
            }
            for (int ee = 0; ee < NEXP; ee++) {
                float q = __fdiv_rn(pbuf[ee], s);
                if (q < FLT_MIN_POS) q = 0.0f;
                pbuf[ee] = q;
            }
            unsigned long long mask = 0ull;
            for (int k = 0; k < TOPK; k++) {
                float bv = -1.0f; int bi = 0;
                for (int ee = 0; ee < NEXP; ee++) {
                    float v = pbuf[ee];
                    if (!((mask >> ee) & 1ull) && v > bv) { bv = v; bi = ee; }
                }
                mask |= (1ull << bi);
            }
            float* __restrict__ gout = out + (size_t)row * NEXP;
            float* __restrict__ mout = out + (size_t)T * NEXP + (size_t)row * NEXP;
            for (int ee = 0; ee < NEXP; ee++) {
                const bool sel = (mask >> ee) & 1ull;
                gout[ee] = sel ? pbuf[ee] : 0.0f;
                mout[ee] = sel ? 1.0f : 0.0f;
            }
        }
        __syncthreads();
    }
}

extern "C" void kernel_launch(void* const* d_in, const int* in_sizes, int n_in,
                              void* d_out, int out_size)
{
    const float* x = (const float*)d_in[0];
    const float* w = (const float*)d_in[1];
    float* out = (float*)d_out;
    const int T = in_sizes[0] / HID;       // 16384
    const int grid = T / BM;               // 256
    router_kernel<<<grid, NTHREADS>>>(x, w, out, T);
}

// round 10
// speedup vs baseline: 9.7262x; 1.0563x over previous
#include <cuda_runtime.h>
#include <math.h>
#include <stdint.h>

// Router: logits = x @ W^T ; softmax ; top-8 ; scatter gates + one-hot map.
// x: [T, 2048] fp32, W: [64, 2048] fp32
// out: [2*T*64] fp32 : first T*64 = dense gates, next T*64 = one-hot map
//
// R10: GEMM moved to tensor cores: mma.sync.m16n8k8 tf32 with 2-term
// precision split (hi*hi + hi*lo + lo*hi) -> logit abs err ~1e-5 (same as
// scalar fp32). Epilogue (softmax-flush + top-8 + guard + fp64 repair) is
// the R7-validated path, unchanged.

#define HID   2048
#define NEXP  64
#define TOPK  8
#define BM    64
#define BK    32
#define NTHREADS 256
#define XS_STRIDE 36
#define FLT_MIN_POS 1.17549435e-38f
#define EXP_CUT     87.336544f
#define GUARD       0.05f
#define GUARD_CUT   0.02f

__device__ __forceinline__ void split_tf32(float v, uint32_t &hi, uint32_t &lo)
{
    asm("cvt.rna.tf32.f32 %0, %1;" : "=r"(hi) : "f"(v));
    float r = v - __uint_as_float(hi);
    asm("cvt.rna.tf32.f32 %0, %1;" : "=r"(lo) : "f"(r));
}

__device__ __forceinline__ void mma_tf32(float &c0, float &c1, float &c2, float &c3,
                                         uint32_t a0, uint32_t a1, uint32_t a2, uint32_t a3,
                                         uint32_t b0, uint32_t b1)
{
    asm volatile(
        "mma.sync.aligned.m16n8k8.row.col.f32.tf32.tf32.f32 "
        "{%0,%1,%2,%3}, {%4,%5,%6,%7}, {%8,%9}, {%0,%1,%2,%3};\n"
        : "+f"(c0), "+f"(c1), "+f"(c2), "+f"(c3)
        : "r"(a0), "r"(a1), "r"(a2), "r"(a3), "r"(b0), "r"(b1));
}

__global__ __launch_bounds__(NTHREADS, 2)
void router_kernel(const float* __restrict__ x,
                   const float* __restrict__ w,
                   float* __restrict__ out,
                   int T)
{
    __shared__ float xs[BM][XS_STRIDE];      // x tile, row-major [row][k]
    __shared__ float ws[NEXP][XS_STRIDE];    // w tile, row-major [expert][k]
    __shared__ float lg[BM][NEXP + 1];       // logits, then d = l - m
    __shared__ float qv[BM][NEXP + 1];       // p, then q = p/s (flushed)
    __shared__ int   flagCnt;
    __shared__ int   flagRows[BM];
    __shared__ double red[4][NEXP];
    __shared__ float  exlog[NEXP];

    const int tid  = threadIdx.x;
    const int lane = tid & 31;
    const int wid  = tid >> 5;         // 8 warps
    const int rg   = wid & 3;          // row group: rows rg*16 .. rg*16+15
    const int cg   = wid >> 2;         // col group: cols cg*32 .. cg*32+31
    const int lr   = lane >> 2;        // 0..7
    const int lc   = lane & 3;         // 0..3
    const int rowBase = blockIdx.x * BM;

    if (tid == 0) flagCnt = 0;

    float acc[4][4];                   // 4 n-tiles x {c0,c1,c2,c3}
#pragma unroll
    for (int i = 0; i < 4; i++)
#pragma unroll
        for (int j = 0; j < 4; j++) acc[i][j] = 0.0f;

    // Global loads: 64 rows x 8 float4 = 512 float4 each for x-tile and w-tile.
    const int f0 = tid, f1 = tid + NTHREADS;
    const int r0 = f0 >> 3, q0 = f0 & 7;
    const int r1 = f1 >> 3, q1 = f1 & 7;

    const float4* __restrict__ xg = (const float4*)x;   // row stride 512
    const float4* __restrict__ wg = (const float4*)w;

    float4 xreg0 = xg[(size_t)(rowBase + r0) * (HID / 4) + q0];
    float4 xreg1 = xg[(size_t)(rowBase + r1) * (HID / 4) + q1];
    float4 wreg0 = wg[(size_t)r0 * (HID / 4) + q0];
    float4 wreg1 = wg[(size_t)r1 * (HID / 4) + q1];

    const int NT = HID / BK;   // 64 K-tiles
    for (int t = 0; t < NT; t++) {
        *(float4*)&xs[r0][q0 * 4] = xreg0;
        *(float4*)&xs[r1][q1 * 4] = xreg1;
        *(float4*)&ws[r0][q0 * 4] = wreg0;
        *(float4*)&ws[r1][q1 * 4] = wreg1;
        __syncthreads();

        if (t + 1 < NT) {
            const int ko = (t + 1) * (BK / 4);
            xreg0 = xg[(size_t)(rowBase + r0) * (HID / 4) + ko + q0];
            xreg1 = xg[(size_t)(rowBase + r1) * (HID / 4) + ko + q1];
            wreg0 = wg[(size_t)r0 * (HID / 4) + ko + q0];
            wreg1 = wg[(size_t)r1 * (HID / 4) + ko + q1];
        }

#pragma unroll
        for (int ks = 0; ks < BK / 8; ks++) {          // 4 mma k-steps
            const int kb = ks * 8;
            // A fragment (16x8) for this warp's row group, split hi/lo
            const int ra0 = rg * 16 + lr, ra1 = ra0 + 8;
            uint32_t ah[4], al[4];
            split_tf32(xs[ra0][kb + lc],     ah[0], al[0]);
            split_tf32(xs[ra1][kb + lc],     ah[1], al[1]);
            split_tf32(xs[ra0][kb + lc + 4], ah[2], al[2]);
            split_tf32(xs[ra1][kb + lc + 4], ah[3], al[3]);

#pragma unroll
            for (int nt = 0; nt < 4; nt++) {           // 4 n-tiles of 8 experts
                const int n0 = cg * 32 + nt * 8;
                uint32_t bh0, bl0, bh1, bl1;
                split_tf32(ws[n0 + lr][kb + lc],     bh0, bl0);
                split_tf32(ws[n0 + lr][kb + lc + 4], bh1, bl1);
                // hi*hi + hi*lo + lo*hi
                mma_tf32(acc[nt][0], acc[nt][1], acc[nt][2], acc[nt][3],
                         ah[0], ah[1], ah[2], ah[3], bh0, bh1);
                mma_tf32(acc[nt][0], acc[nt][1], acc[nt][2], acc[nt][3],
                         ah[0], ah[1], ah[2], ah[3], bl0, bl1);
                mma_tf32(acc[nt][0], acc[nt][1], acc[nt][2], acc[nt][3],
                         al[0], al[1], al[2], al[3], bh0, bh1);
            }
        }
        __syncthreads();
    }

    // Dump accumulators -> logits smem. C layout of m16n8:
    // c0:(lr, lc*2) c1:(lr, lc*2+1) c2:(lr+8, lc*2) c3:(lr+8, lc*2+1)
#pragma unroll
    for (int nt = 0; nt < 4; nt++) {
        const int col = cg * 32 + nt * 8 + lc * 2;
        lg[rg * 16 + lr][col]         = acc[nt][0];
        lg[rg * 16 + lr][col + 1]     = acc[nt][1];
        lg[rg * 16 + lr + 8][col]     = acc[nt][2];
        lg[rg * 16 + lr + 8][col + 1] = acc[nt][3];
    }
    __syncthreads();

    // ── Fast epilogue: one thread per row (R7-validated) ────────────────
    if (tid < BM) {
        const int row = rowBase + tid;

        float m = -1e30f;
#pragma unroll
        for (int e = 0; e < NEXP; e++) m = fmaxf(m, lg[tid][e]);

        float s = 0.0f;
#pragma unroll
        for (int e = 0; e < NEXP; e++) {
            float d = lg[tid][e] - m;
            lg[tid][e] = d;
            float p = expf(d);
            if (p < FLT_MIN_POS) p = 0.0f;       // exp flush (R2->R3 evidence)
            qv[tid][e] = p;
            s += p;
        }

#pragma unroll
        for (int e = 0; e < NEXP; e++) {
            float q = __fdiv_rn(qv[tid][e], s);
            if (q < FLT_MIN_POS) q = 0.0f;       // division flush band
            qv[tid][e] = q;
        }

        unsigned long long mask = 0ull;
        for (int k = 0; k < TOPK; k++) {
            float bv = -1.0f; int bi = 0;
            for (int e = 0; e < NEXP; e++) {
                float v = qv[tid][e];
                if (!((mask >> e) & 1ull) && v > bv) { bv = v; bi = e; }
            }
            mask |= (1ull << bi);
        }

        // Robustness guard
        int nA = 0;
        float d8 = 1e30f, d9 = -1e30f;
#pragma unroll
        for (int e = 0; e < NEXP; e++) {
            bool pos = qv[tid][e] > 0.0f;
            bool sel = (mask >> e) & 1ull;
            if (pos) {
                nA++;
                if (sel)  d8 = fminf(d8, lg[tid][e]);
                else      d9 = fmaxf(d9, lg[tid][e]);
            }
        }
        bool flag = false;
        if (d9 > -1e29f && (d8 - d9) < GUARD) flag = true;
        if (nA <= 8) {
            float c = logf(s) - EXP_CUT;
#pragma unroll
            for (int e = 0; e < NEXP; e++)
                if (fabsf(lg[tid][e] - c) < GUARD_CUT) flag = true;
        }

        if (!flag) {
            float* __restrict__ gout = out + (size_t)row * NEXP;
            float* __restrict__ mout = out + (size_t)T * NEXP + (size_t)row * NEXP;
#pragma unroll
            for (int e = 0; e < NEXP; e++) {
                const bool sel = (mask >> e) & 1ull;
                gout[e] = sel ? qv[tid][e] : 0.0f;
                mout[e] = sel ? 1.0f : 0.0f;
            }
        } else {
            flagRows[atomicAdd(&flagCnt, 1)] = tid;
        }
    }
    __syncthreads();

    // ── Exact fp64 repair for flagged rows (whole block per row) ────────
    const int nf = flagCnt;
    for (int r = 0; r < nf; r++) {
        const int lrow = flagRows[r];
        const int row  = rowBase + lrow;
        const int e    = tid & 63;
        const int ch   = tid >> 6;             // 4 chunks of 512 elements

        const float4* xr = xg + (size_t)row * (HID / 4) + ch * 128;
        const float4* wr = wg + (size_t)e   * (HID / 4) + ch * 128;
        double a0 = 0.0, a1 = 0.0, a2 = 0.0, a3 = 0.0;
#pragma unroll 4
        for (int i = 0; i < 128; i++) {
            float4 xv = xr[i], wv = wr[i];
            a0 = fma((double)xv.x, (double)wv.x, a0);
            a1 = fma((double)xv.y, (double)wv.y, a1);
            a2 = fma((double)xv.z, (double)wv.z, a2);
            a3 = fma((double)xv.w, (double)wv.w, a3);
        }
        red[ch][e] = (a0 + a1) + (a2 + a3);
        __syncthreads();
        if (tid < NEXP)
            exlog[tid] = (float)((red[0][tid] + red[1][tid]) +
                                 (red[2][tid] + red[3][tid]));
        __syncthreads();

        if (tid == 0) {
            float m = -1e30f;
            for (int ee = 0; ee < NEXP; ee++) m = fmaxf(m, exlog[ee]);
            float s = 0.0f;
            float pbuf[NEXP];
            for (int ee = 0; ee < NEXP; ee++) {
                float p = expf(exlog[ee] - m);
                if (p < FLT_MIN_POS) p = 0.0f;
                pbuf[ee] = p;
                s += p;
            }
            for (int ee = 0; ee < NEXP; ee++) {
                float q = __fdiv_rn(pbuf[ee], s);
                if (q < FLT_MIN_POS) q = 0.0f;
                pbuf[ee] = q;
            }
            unsigned long long mask = 0ull;
            for (int k = 0; k < TOPK; k++) {
                float bv = -1.0f; int bi = 0;
                for (int ee = 0; ee < NEXP; ee++) {
                    float v = pbuf[ee];
                    if (!((mask >> ee) & 1ull) && v > bv) { bv = v; bi = ee; }
                }
                mask |= (1ull << bi);
            }
            float* __restrict__ gout = out + (size_t)row * NEXP;
            float* __restrict__ mout = out + (size_t)T * NEXP + (size_t)row * NEXP;
            for (int ee = 0; ee < NEXP; ee++) {
                const bool sel = (mask >> ee) & 1ull;
                gout[ee] = sel ? pbuf[ee] : 0.0f;
                mout[ee] = sel ? 1.0f : 0.0f;
            }
        }
        __syncthreads();
    }
}

extern "C" void kernel_launch(void* const* d_in, const int* in_sizes, int n_in,
                              void* d_out, int out_size)
{
    const float* x = (const float*)d_in[0];
    const float* w = (const float*)d_in[1];
    float* out = (float*)d_out;
    const int T = in_sizes[0] / HID;       // 16384
    const int grid = T / BM;               // 256
    router_kernel<<<grid, NTHREADS>>>(x, w, out, T);
}

// round 11
// speedup vs baseline: 9.8590x; 1.0137x over previous
#include <cuda_runtime.h>
#include <math.h>
#include <stdint.h>

// Router: logits = x @ W^T ; softmax ; top-8 ; scatter gates + one-hot map.
// x: [T, 2048] fp32, W: [64, 2048] fp32
// out: [2*T*64] fp32 : first T*64 = dense gates, next T*64 = one-hot map
//
// R11: tf32 3-term split GEMM, restructured for latency:
//  - producers split x/w into tf32 hi/lo ONCE, store to smem (consumers LDS->MMA only)
//  - two accumulator sets (P=hi*hi, Q=hi*lo+lo*hi) break HMMA RAW chains
//  - double-buffered smem, ONE __syncthreads per K-tile
//  - epilogue buffers union-overlay the GEMM stages (dynamic smem, 2 CTAs/SM)
// Epilogue/guard/fp64-repair identical to the validated R7/R10 path.

#define HID   2048
#define NEXP  64
#define TOPK  8
#define BM    64
#define BK    32
#define NTHREADS 256
#define KS    36                      // padded k-stride (bank-stagger)
#define FLT_MIN_POS 1.17549435e-38f
#define EXP_CUT     87.336544f
#define GUARD       0.05f
#define GUARD_CUT   0.02f

struct GemmBufs {
    uint32_t xh[2][BM][KS];
    uint32_t xl[2][BM][KS];
    uint32_t wh[2][NEXP][KS];
    uint32_t wl[2][NEXP][KS];
};
struct EpiBufs {
    float  lg[BM][NEXP + 1];
    float  qv[BM][NEXP + 1];
    double red[4][NEXP];
    float  exlog[NEXP];
    int    flagCnt;
    int    flagRows[BM];
};
union SmemU { GemmBufs g; EpiBufs e; };

__device__ __forceinline__ void split_tf32(float v, uint32_t &hi, uint32_t &lo)
{
    asm("cvt.rna.tf32.f32 %0, %1;" : "=r"(hi) : "f"(v));
    float r = v - __uint_as_float(hi);
    asm("cvt.rna.tf32.f32 %0, %1;" : "=r"(lo) : "f"(r));
}

__device__ __forceinline__ void split_store4(uint32_t* hp, uint32_t* lp, float4 v)
{
    uint32_t h0, h1, h2, h3, l0, l1, l2, l3;
    split_tf32(v.x, h0, l0); split_tf32(v.y, h1, l1);
    split_tf32(v.z, h2, l2); split_tf32(v.w, h3, l3);
    *reinterpret_cast<uint4*>(hp) = make_uint4(h0, h1, h2, h3);
    *reinterpret_cast<uint4*>(lp) = make_uint4(l0, l1, l2, l3);
}

__device__ __forceinline__ void mma_tf32(float &c0, float &c1, float &c2, float &c3,
                                         uint32_t a0, uint32_t a1, uint32_t a2, uint32_t a3,
                                         uint32_t b0, uint32_t b1)
{
    asm volatile(
        "mma.sync.aligned.m16n8k8.row.col.f32.tf32.tf32.f32 "
        "{%0,%1,%2,%3}, {%4,%5,%6,%7}, {%8,%9}, {%0,%1,%2,%3};\n"
        : "+f"(c0), "+f"(c1), "+f"(c2), "+f"(c3)
        : "r"(a0), "r"(a1), "r"(a2), "r"(a3), "r"(b0), "r"(b1));
}

__global__ __launch_bounds__(NTHREADS, 2)
void router_kernel(const float* __restrict__ x,
                   const float* __restrict__ w,
                   float* __restrict__ out,
                   int T)
{
    extern __shared__ char smraw[];
    SmemU& S = *reinterpret_cast<SmemU*>(smraw);

    const int tid  = threadIdx.x;
    const int lane = tid & 31;
    const int wid  = tid >> 5;         // 8 warps
    const int rg   = wid & 3;          // rows rg*16 .. +15
    const int cg   = wid >> 2;         // experts cg*32 .. +31
    const int lr   = lane >> 2;        // 0..7
    const int lc   = lane & 3;         // 0..3
    const int rowBase = blockIdx.x * BM;

    float accP[4][4], accQ[4][4];
#pragma unroll
    for (int i = 0; i < 4; i++)
#pragma unroll
        for (int j = 0; j < 4; j++) { accP[i][j] = 0.0f; accQ[i][j] = 0.0f; }

    // Global loads: each tile is 64 rows x 8 float4; thread covers f0 and f1.
    const int f0 = tid, f1 = tid + NTHREADS;
    const int r0 = f0 >> 3, q0 = f0 & 7;
    const int r1 = f1 >> 3, q1 = f1 & 7;

    const float4* __restrict__ xg = (const float4*)x;   // row stride 512
    const float4* __restrict__ wg = (const float4*)w;

    float4 xr0 = xg[(size_t)(rowBase + r0) * (HID / 4) + q0];
    float4 xr1 = xg[(size_t)(rowBase + r1) * (HID / 4) + q1];
    float4 wr0 = wg[(size_t)r0 * (HID / 4) + q0];
    float4 wr1 = wg[(size_t)r1 * (HID / 4) + q1];

    // Prologue: stage 0
    split_store4(&S.g.xh[0][r0][q0 * 4], &S.g.xl[0][r0][q0 * 4], xr0);
    split_store4(&S.g.xh[0][r1][q1 * 4], &S.g.xl[0][r1][q1 * 4], xr1);
    split_store4(&S.g.wh[0][r0][q0 * 4], &S.g.wl[0][r0][q0 * 4], wr0);
    split_store4(&S.g.wh[0][r1][q1 * 4], &S.g.wl[0][r1][q1 * 4], wr1);
    __syncthreads();

    const int NT = HID / BK;           // 64 K-tiles
    for (int t = 0; t < NT; t++) {
        const int st = t & 1;

        if (t + 1 < NT) {              // async prefetch next tile into regs
            const int ko = (t + 1) * (BK / 4);
            xr0 = xg[(size_t)(rowBase + r0) * (HID / 4) + ko + q0];
            xr1 = xg[(size_t)(rowBase + r1) * (HID / 4) + ko + q1];
            wr0 = wg[(size_t)r0 * (HID / 4) + ko + q0];
            wr1 = wg[(size_t)r1 * (HID / 4) + ko + q1];
        }

        // Consume stage st: pure LDS -> HMMA
#pragma unroll
        for (int ks_ = 0; ks_ < BK / 8; ks_++) {
            const int kb  = ks_ * 8;
            const int ra0 = rg * 16 + lr, ra1 = ra0 + 8;

            uint32_t ah0 = S.g.xh[st][ra0][kb + lc];
            uint32_t ah1 = S.g.xh[st][ra1][kb + lc];
            uint32_t ah2 = S.g.xh[st][ra0][kb + lc + 4];
            uint32_t ah3 = S.g.xh[st][ra1][kb + lc + 4];
            uint32_t al0 = S.g.xl[st][ra0][kb + lc];
            uint32_t al1 = S.g.xl[st][ra1][kb + lc];
            uint32_t al2 = S.g.xl[st][ra0][kb + lc + 4];
            uint32_t al3 = S.g.xl[st][ra1][kb + lc + 4];

            uint32_t bh[4][2], bl[4][2];
#pragma unroll
            for (int nt = 0; nt < 4; nt++) {
                const int nr = cg * 32 + nt * 8 + lr;
                bh[nt][0] = S.g.wh[st][nr][kb + lc];
                bh[nt][1] = S.g.wh[st][nr][kb + lc + 4];
                bl[nt][0] = S.g.wl[st][nr][kb + lc];
                bl[nt][1] = S.g.wl[st][nr][kb + lc + 4];
            }
#pragma unroll
            for (int nt = 0; nt < 4; nt++)
                mma_tf32(accP[nt][0], accP[nt][1], accP[nt][2], accP[nt][3],
                         ah0, ah1, ah2, ah3, bh[nt][0], bh[nt][1]);
#pragma unroll
            for (int nt = 0; nt < 4; nt++)
                mma_tf32(accQ[nt][0], accQ[nt][1], accQ[nt][2], accQ[nt][3],
                         ah0, ah1, ah2, ah3, bl[nt][0], bl[nt][1]);
#pragma unroll
            for (int nt = 0; nt < 4; nt++)
                mma_tf32(accQ[nt][0], accQ[nt][1], accQ[nt][2], accQ[nt][3],
                         al0, al1, al2, al3, bh[nt][0], bh[nt][1]);
        }

        if (t + 1 < NT) {              // fill the other stage
            const int sn = st ^ 1;
            split_store4(&S.g.xh[sn][r0][q0 * 4], &S.g.xl[sn][r0][q0 * 4], xr0);
            split_store4(&S.g.xh[sn][r1][q1 * 4], &S.g.xl[sn][r1][q1 * 4], xr1);
            split_store4(&S.g.wh[sn][r0][q0 * 4], &S.g.wl[sn][r0][q0 * 4], wr0);
            split_store4(&S.g.wh[sn][r1][q1 * 4], &S.g.wl[sn][r1][q1 * 4], wr1);
        }
        __syncthreads();
    }

    // Dump merged accumulators -> logits (overlays dead GEMM buffers).
    // C layout of m16n8: c0:(lr,lc*2) c1:(lr,lc*2+1) c2:(lr+8,..) c3:(lr+8,..+1)
#pragma unroll
    for (int nt = 0; nt < 4; nt++) {
        const int col = cg * 32 + nt * 8 + lc * 2;
        S.e.lg[rg * 16 + lr][col]         = accP[nt][0] + accQ[nt][0];
        S.e.lg[rg * 16 + lr][col + 1]     = accP[nt][1] + accQ[nt][1];
        S.e.lg[rg * 16 + lr + 8][col]     = accP[nt][2] + accQ[nt][2];
        S.e.lg[rg * 16 + lr + 8][col + 1] = accP[nt][3] + accQ[nt][3];
    }
    if (tid == 0) S.e.flagCnt = 0;
    __syncthreads();

    // ── Fast epilogue: one thread per row (R7/R10-validated) ────────────
    if (tid < BM) {
        const int row = rowBase + tid;

        float m = -1e30f;
#pragma unroll
        for (int e = 0; e < NEXP; e++) m = fmaxf(m, S.e.lg[tid][e]);

        float s = 0.0f;
#pragma unroll
        for (int e = 0; e < NEXP; e++) {
            float d = S.e.lg[tid][e] - m;
            S.e.lg[tid][e] = d;
            float p = expf(d);
            if (p < FLT_MIN_POS) p = 0.0f;       // exp flush (R2->R3 evidence)
            S.e.qv[tid][e] = p;
            s += p;
        }

#pragma unroll
        for (int e = 0; e < NEXP; e++) {
            float q = __fdiv_rn(S.e.qv[tid][e], s);
            if (q < FLT_MIN_POS) q = 0.0f;       // division flush band
            S.e.qv[tid][e] = q;
        }

        unsigned long long mask = 0ull;
        for (int k = 0; k < TOPK; k++) {
            float bv = -1.0f; int bi = 0;
            for (int e = 0; e < NEXP; e++) {
                float v = S.e.qv[tid][e];
                if (!((mask >> e) & 1ull) && v > bv) { bv = v; bi = e; }
            }
            mask |= (1ull << bi);
        }

        // Robustness guard
        int nA = 0;
        float d8 = 1e30f, d9 = -1e30f;
#pragma unroll
        for (int e = 0; e < NEXP; e++) {
            bool pos = S.e.qv[tid][e] > 0.0f;
            bool sel = (mask >> e) & 1ull;
            if (pos) {
                nA++;
                if (sel)  d8 = fminf(d8, S.e.lg[tid][e]);
                else      d9 = fmaxf(d9, S.e.lg[tid][e]);
            }
        }
        bool flag = false;
        if (d9 > -1e29f && (d8 - d9) < GUARD) flag = true;
        if (nA <= 8) {
            float c = logf(s) - EXP_CUT;
#pragma unroll
            for (int e = 0; e < NEXP; e++)
                if (fabsf(S.e.lg[tid][e] - c) < GUARD_CUT) flag = true;
        }

        if (!flag) {
            float* __restrict__ gout = out + (size_t)row * NEXP;
            float* __restrict__ mout = out + (size_t)T * NEXP + (size_t)row * NEXP;
#pragma unroll
            for (int e = 0; e < NEXP; e++) {
                const bool sel = (mask >> e) & 1ull;
                gout[e] = sel ? S.e.qv[tid][e] : 0.0f;
                mout[e] = sel ? 1.0f : 0.0f;
            }
        } else {
            S.e.flagRows[atomicAdd(&S.e.flagCnt, 1)] = tid;
        }
    }
    __syncthreads();

    // ── Exact fp64 repair for flagged rows (whole block per row) ────────
    const int nf = S.e.flagCnt;
    for (int r = 0; r < nf; r++) {
        const int lrow = S.e.flagRows[r];
        const int row  = rowBase + lrow;
        const int e    = tid & 63;
        const int ch   = tid >> 6;             // 4 chunks of 512 elements

        const float4* xr = xg + (size_t)row * (HID / 4) + ch * 128;
        const float4* wr = wg + (size_t)e   * (HID / 4) + ch * 128;
        double a0 = 0.0, a1 = 0.0, a2 = 0.0, a3 = 0.0;
#pragma unroll 4
        for (int i = 0; i < 128; i++) {
            float4 xv = xr[i], wv = wr[i];
            a0 = fma((double)xv.x, (double)wv.x, a0);
            a1 = fma((double)xv.y, (double)wv.y, a1);
            a2 = fma((double)xv.z, (double)wv.z, a2);
            a3 = fma((double)xv.w, (double)wv.w, a3);
        }
        S.e.red[ch][e] = (a0 + a1) + (a2 + a3);
        __syncthreads();
        if (tid < NEXP)
            S.e.exlog[tid] = (float)((S.e.red[0][tid] + S.e.red[1][tid]) +
                                     (S.e.red[2][tid] + S.e.red[3][tid]));
        __syncthreads();

        if (tid == 0) {
            float m = -1e30f;
            for (int ee = 0; ee < NEXP; ee++) m = fmaxf(m, S.e.exlog[ee]);
            float s = 0.0f;
            float pbuf[NEXP];
            for (int ee = 0; ee < NEXP; ee++) {
                float p = expf(S.e.exlog[ee] - m);
                if (p < FLT_MIN_POS) p = 0.0f;
                pbuf[ee] = p;
                s += p;
            }
            for (int ee = 0; ee < NEXP; ee++) {
                float q = __fdiv_rn(pbuf[ee], s);
                if (q < FLT_MIN_POS) q = 0.0f;
                pbuf[ee] = q;
            }
            unsigned long long mask = 0ull;
            for (int k = 0; k < TOPK; k++) {
                float bv = -1.0f; int bi = 0;
                for (int ee = 0; ee < NEXP; ee++) {
                    float v = pbuf[ee];
                    if (!((mask >> ee) & 1ull) && v > bv) { bv = v; bi = ee; }
                }
                mask |= (1ull << bi);
            }
            float* __restrict__ gout = out + (size_t)row * NEXP;
            float* __restrict__ mout = out + (size_t)T * NEXP + (size_t)row * NEXP;
            for (int ee = 0; ee < NEXP; ee++) {
                const bool sel = (mask >> ee) & 1ull;
                gout[ee] = sel ? pbuf[ee] : 0.0f;
                mout[ee] = sel ? 1.0f : 0.0f;
            }
        }
        __syncthreads();
    }
}

extern "C" void kernel_launch(void* const* d_in, const int* in_sizes, int n_in,
                              void* d_out, int out_size)
{
    const float* x = (const float*)d_in[0];
    const float* w = (const float*)d_in[1];
    float* out = (float*)d_out;
    const int T = in_sizes[0] / HID;       // 16384
    const int grid = T / BM;               // 256
    const int smem = (int)sizeof(SmemU);   // 73728 B
    cudaFuncSetAttribute(router_kernel,
                         cudaFuncAttributeMaxDynamicSharedMemorySize, smem);
    router_kernel<<<grid, NTHREADS, smem>>>(x, w, out, T);
}

// round 13
// speedup vs baseline: 33.0888x; 3.3562x over previous
#include <cuda_runtime.h>
#include <math.h>
#include <stdint.h>

// Router: logits = x @ W^T ; softmax ; top-8 ; scatter gates + one-hot map.
// x: [T, 2048] fp32, W: [64, 2048] fp32
// out: [2*T*64] fp32 : first T*64 = dense gates, next T*64 = one-hot map
//
// R12: fp64 repair replaced by fp32 TwoProd+Kahan compensated dots (GB300
// fp64 vector measured ~1.2 DFMA/cyc/SM via R6: the repair tail WAS the
// ~700us floor of R9-R11). Guards tightened 0.05->0.015 (tf32-split logit
// err ~5e-5). Mainloop identical to R11.

#define HID   2048
#define NEXP  64
#define TOPK  8
#define BM    64
#define BK    32
#define NTHREADS 256
#define KS    36                      // padded k-stride (bank-stagger)
#define FLT_MIN_POS 1.17549435e-38f
#define EXP_CUT     87.336544f
#define GUARD       0.015f
#define GUARD_CUT   0.015f

struct GemmBufs {
    uint32_t xh[2][BM][KS];
    uint32_t xl[2][BM][KS];
    uint32_t wh[2][NEXP][KS];
    uint32_t wl[2][NEXP][KS];
};
struct EpiBufs {
    float  lg[BM][NEXP + 1];
    float  qv[BM][NEXP + 1];
    float  red[4][NEXP];
    float  exlog[NEXP];
    int    flagCnt;
    int    flagRows[BM];
};
union SmemU { GemmBufs g; EpiBufs e; };

__device__ __forceinline__ void split_tf32(float v, uint32_t &hi, uint32_t &lo)
{
    asm("cvt.rna.tf32.f32 %0, %1;" : "=r"(hi) : "f"(v));
    float r = v - __uint_as_float(hi);
    asm("cvt.rna.tf32.f32 %0, %1;" : "=r"(lo) : "f"(r));
}

__device__ __forceinline__ void split_store4(uint32_t* hp, uint32_t* lp, float4 v)
{
    uint32_t h0, h1, h2, h3, l0, l1, l2, l3;
    split_tf32(v.x, h0, l0); split_tf32(v.y, h1, l1);
    split_tf32(v.z, h2, l2); split_tf32(v.w, h3, l3);
    *reinterpret_cast<uint4*>(hp) = make_uint4(h0, h1, h2, h3);
    *reinterpret_cast<uint4*>(lp) = make_uint4(l0, l1, l2, l3);
}

__device__ __forceinline__ void mma_tf32(float &c0, float &c1, float &c2, float &c3,
                                         uint32_t a0, uint32_t a1, uint32_t a2, uint32_t a3,
                                         uint32_t b0, uint32_t b1)
{
    asm volatile(
        "mma.sync.aligned.m16n8k8.row.col.f32.tf32.tf32.f32 "
        "{%0,%1,%2,%3}, {%4,%5,%6,%7}, {%8,%9}, {%0,%1,%2,%3};\n"
        : "+f"(c0), "+f"(c1), "+f"(c2), "+f"(c3)
        : "r"(a0), "r"(a1), "r"(a2), "r"(a3), "r"(b0), "r"(b1));
}

// TwoProd + Kahan step: add x*w exactly-ish into (s, c). Effective sum = s - c.
__device__ __forceinline__ void comp_fma(float xv, float wv, float &s, float &c)
{
    float p = xv * wv;
    float e = fmaf(xv, wv, -p);      // exact product low part
    float y = p - c;
    float t = s + y;
    c = (t - s) - y;                 // rounding excess of the add
    c -= e;                          // fold product low part into compensation
    s = t;
}

__global__ __launch_bounds__(NTHREADS, 2)
void router_kernel(const float* __restrict__ x,
                   const float* __restrict__ w,
                   float* __restrict__ out,
                   int T)
{
    extern __shared__ char smraw[];
    SmemU& S = *reinterpret_cast<SmemU*>(smraw);

    const int tid  = threadIdx.x;
    const int lane = tid & 31;
    const int wid  = tid >> 5;         // 8 warps
    const int rg   = wid & 3;          // rows rg*16 .. +15
    const int cg   = wid >> 2;         // experts cg*32 .. +31
    const int lr   = lane >> 2;        // 0..7
    const int lc   = lane & 3;         // 0..3
    const int rowBase = blockIdx.x * BM;

    float accP[4][4], accQ[4][4];
#pragma unroll
    for (int i = 0; i < 4; i++)
#pragma unroll
        for (int j = 0; j < 4; j++) { accP[i][j] = 0.0f; accQ[i][j] = 0.0f; }

    const int f0 = tid, f1 = tid + NTHREADS;
    const int r0 = f0 >> 3, q0 = f0 & 7;
    const int r1 = f1 >> 3, q1 = f1 & 7;

    const float4* __restrict__ xg = (const float4*)x;   // row stride 512
    const float4* __restrict__ wg = (const float4*)w;

    float4 xr0 = xg[(size_t)(rowBase + r0) * (HID / 4) + q0];
    float4 xr1 = xg[(size_t)(rowBase + r1) * (HID / 4) + q1];
    float4 wr0 = wg[(size_t)r0 * (HID / 4) + q0];
    float4 wr1 = wg[(size_t)r1 * (HID / 4) + q1];

    split_store4(&S.g.xh[0][r0][q0 * 4], &S.g.xl[0][r0][q0 * 4], xr0);
    split_store4(&S.g.xh[0][r1][q1 * 4], &S.g.xl[0][r1][q1 * 4], xr1);
    split_store4(&S.g.wh[0][r0][q0 * 4], &S.g.wl[0][r0][q0 * 4], wr0);
    split_store4(&S.g.wh[0][r1][q1 * 4], &S.g.wl[0][r1][q1 * 4], wr1);
    __syncthreads();

    const int NT = HID / BK;           // 64 K-tiles
    for (int t = 0; t < NT; t++) {
        const int st = t & 1;

        if (t + 1 < NT) {
            const int ko = (t + 1) * (BK / 4);
            xr0 = xg[(size_t)(rowBase + r0) * (HID / 4) + ko + q0];
            xr1 = xg[(size_t)(rowBase + r1) * (HID / 4) + ko + q1];
            wr0 = wg[(size_t)r0 * (HID / 4) + ko + q0];
            wr1 = wg[(size_t)r1 * (HID / 4) + ko + q1];
        }

#pragma unroll
        for (int ks_ = 0; ks_ < BK / 8; ks_++) {
            const int kb  = ks_ * 8;
            const int ra0 = rg * 16 + lr, ra1 = ra0 + 8;

            uint32_t ah0 = S.g.xh[st][ra0][kb + lc];
            uint32_t ah1 = S.g.xh[st][ra1][kb + lc];
            uint32_t ah2 = S.g.xh[st][ra0][kb + lc + 4];
            uint32_t ah3 = S.g.xh[st][ra1][kb + lc + 4];
            uint32_t al0 = S.g.xl[st][ra0][kb + lc];
            uint32_t al1 = S.g.xl[st][ra1][kb + lc];
            uint32_t al2 = S.g.xl[st][ra0][kb + lc + 4];
            uint32_t al3 = S.g.xl[st][ra1][kb + lc + 4];

            uint32_t bh[4][2], bl[4][2];
#pragma unroll
            for (int nt = 0; nt < 4; nt++) {
                const int nr = cg * 32 + nt * 8 + lr;
                bh[nt][0] = S.g.wh[st][nr][kb + lc];
                bh[nt][1] = S.g.wh[st][nr][kb + lc + 4];
                bl[nt][0] = S.g.wl[st][nr][kb + lc];
                bl[nt][1] = S.g.wl[st][nr][kb + lc + 4];
            }
#pragma unroll
            for (int nt = 0; nt < 4; nt++)
                mma_tf32(accP[nt][0], accP[nt][1], accP[nt][2], accP[nt][3],
                         ah0, ah1, ah2, ah3, bh[nt][0], bh[nt][1]);
#pragma unroll
            for (int nt = 0; nt < 4; nt++)
                mma_tf32(accQ[nt][0], accQ[nt][1], accQ[nt][2], accQ[nt][3],
                         ah0, ah1, ah2, ah3, bl[nt][0], bl[nt][1]);
#pragma unroll
            for (int nt = 0; nt < 4; nt++)
                mma_tf32(accQ[nt][0], accQ[nt][1], accQ[nt][2], accQ[nt][3],
                         al0, al1, al2, al3, bh[nt][0], bh[nt][1]);
        }

        if (t + 1 < NT) {
            const int sn = st ^ 1;
            split_store4(&S.g.xh[sn][r0][q0 * 4], &S.g.xl[sn][r0][q0 * 4], xr0);
            split_store4(&S.g.xh[sn][r1][q1 * 4], &S.g.xl[sn][r1][q1 * 4], xr1);
            split_store4(&S.g.wh[sn][r0][q0 * 4], &S.g.wl[sn][r0][q0 * 4], wr0);
            split_store4(&S.g.wh[sn][r1][q1 * 4], &S.g.wl[sn][r1][q1 * 4], wr1);
        }
        __syncthreads();
    }

    // Dump merged accumulators -> logits (overlays dead GEMM buffers).
#pragma unroll
    for (int nt = 0; nt < 4; nt++) {
        const int col = cg * 32 + nt * 8 + lc * 2;
        S.e.lg[rg * 16 + lr][col]         = accP[nt][0] + accQ[nt][0];
        S.e.lg[rg * 16 + lr][col + 1]     = accP[nt][1] + accQ[nt][1];
        S.e.lg[rg * 16 + lr + 8][col]     = accP[nt][2] + accQ[nt][2];
        S.e.lg[rg * 16 + lr + 8][col + 1] = accP[nt][3] + accQ[nt][3];
    }
    if (tid == 0) S.e.flagCnt = 0;
    __syncthreads();

    // ── Fast epilogue: one thread per row (R7/R10/R11-validated) ────────
    if (tid < BM) {
        const int row = rowBase + tid;

        float m = -1e30f;
#pragma unroll
        for (int e = 0; e < NEXP; e++) m = fmaxf(m, S.e.lg[tid][e]);

        float s = 0.0f;
#pragma unroll
        for (int e = 0; e < NEXP; e++) {
            float d = S.e.lg[tid][e] - m;
            S.e.lg[tid][e] = d;
            float p = expf(d);
            if (p < FLT_MIN_POS) p = 0.0f;       // exp flush (R2->R3 evidence)
            S.e.qv[tid][e] = p;
            s += p;
        }

#pragma unroll
        for (int e = 0; e < NEXP; e++) {
            float q = __fdiv_rn(S.e.qv[tid][e], s);
            if (q < FLT_MIN_POS) q = 0.0f;       // division flush band
            S.e.qv[tid][e] = q;
        }

        unsigned long long mask = 0ull;
        for (int k = 0; k < TOPK; k++) {
            float bv = -1.0f; int bi = 0;
            for (int e = 0; e < NEXP; e++) {
                float v = S.e.qv[tid][e];
                if (!((mask >> e) & 1ull) && v > bv) { bv = v; bi = e; }
            }
            mask |= (1ull << bi);
        }

        // Robustness guard
        int nA = 0;
        float d8 = 1e30f, d9 = -1e30f;
#pragma unroll
        for (int e = 0; e < NEXP; e++) {
            bool pos = S.e.qv[tid][e] > 0.0f;
            bool sel = (mask >> e) & 1ull;
            if (pos) {
                nA++;
                if (sel)  d8 = fminf(d8, S.e.lg[tid][e]);
                else      d9 = fmaxf(d9, S.e.lg[tid][e]);
            }
        }
        bool flag = false;
        if (d9 > -1e29f && (d8 - d9) < GUARD) flag = true;
        if (nA <= 8) {
            float c = logf(s) - EXP_CUT;
#pragma unroll
            for (int e = 0; e < NEXP; e++)
                if (fabsf(S.e.lg[tid][e] - c) < GUARD_CUT) flag = true;
        }

        if (!flag) {
            float* __restrict__ gout = out + (size_t)row * NEXP;
            float* __restrict__ mout = out + (size_t)T * NEXP + (size_t)row * NEXP;
#pragma unroll
            for (int e = 0; e < NEXP; e++) {
                const bool sel = (mask >> e) & 1ull;
                gout[e] = sel ? S.e.qv[tid][e] : 0.0f;
                mout[e] = sel ? 1.0f : 0.0f;
            }
        } else {
            S.e.flagRows[atomicAdd(&S.e.flagCnt, 1)] = tid;
        }
    }
    __syncthreads();

    // ── High-precision fp32 repair for flagged rows (TwoProd + Kahan) ───
    const int nf = S.e.flagCnt;
    for (int r = 0; r < nf; r++) {
        const int lrow = S.e.flagRows[r];
        const int row  = rowBase + lrow;
        const int e    = tid & 63;
        const int ch   = tid >> 6;             // 4 chunks of 512 elements

        const float4* xr = xg + (size_t)row * (HID / 4) + ch * 128;
        const float4* wr = wg + (size_t)e   * (HID / 4) + ch * 128;
        float s0 = 0.f, c0 = 0.f, s1 = 0.f, c1 = 0.f;
        float s2 = 0.f, c2 = 0.f, s3 = 0.f, c3 = 0.f;
#pragma unroll 4
        for (int i = 0; i < 128; i++) {
            float4 xv = xr[i], wv = wr[i];
            comp_fma(xv.x, wv.x, s0, c0);
            comp_fma(xv.y, wv.y, s1, c1);
            comp_fma(xv.z, wv.z, s2, c2);
            comp_fma(xv.w, wv.w, s3, c3);
        }
        S.e.red[ch][e] = ((s0 - c0) + (s1 - c1)) + ((s2 - c2) + (s3 - c3));
        __syncthreads();
        if (tid < NEXP)
            S.e.exlog[tid] = (S.e.red[0][tid] + S.e.red[1][tid]) +
                             (S.e.red[2][tid] + S.e.red[3][tid]);
        __syncthreads();

        if (tid == 0) {
            float m = -1e30f;
            for (int ee = 0; ee < NEXP; ee++) m = fmaxf(m, S.e.exlog[ee]);
            float s = 0.0f;
            float pbuf[NEXP];
            for (int ee = 0; ee < NEXP; ee++) {
                float p = expf(S.e.exlog[ee] - m);
                if (p < FLT_MIN_POS) p = 0.0f;
                pbuf[ee] = p;
                s += p;
            }
            for (int ee = 0; ee < NEXP; ee++) {
                float q = __fdiv_rn(pbuf[ee], s);
                if (q < FLT_MIN_POS) q = 0.0f;
                pbuf[ee] = q;
            }
            unsigned long long mask = 0ull;
            for (int k = 0; k < TOPK; k++) {
                float bv = -1.0f; int bi = 0;
                for (int ee = 0; ee < NEXP; ee++) {
                    float v = pbuf[ee];
                    if (!((mask >> ee) & 1ull) && v > bv) { bv = v; bi = ee; }
                }
                mask |= (1ull << bi);
            }
            float* __restrict__ gout = out + (size_t)row * NEXP;
            float* __restrict__ mout = out + (size_t)T * NEXP + (size_t)row * NEXP;
            for (int ee = 0; ee < NEXP; ee++) {
                const bool sel = (mask >> ee) & 1ull;
                gout[ee] = sel ? pbuf[ee] : 0.0f;
                mout[ee] = sel ? 1.0f : 0.0f;
            }
        }
        __syncthreads();
    }
}

extern "C" void kernel_launch(void* const* d_in, const int* in_sizes, int n_in,
                              void* d_out, int out_size)
{
    const float* x = (const float*)d_in[0];
    const float* w = (const float*)d_in[1];
    float* out = (float*)d_out;
    const int T = in_sizes[0] / HID;       // 16384
    const int grid = T / BM;               // 256
    const int smem = (int)sizeof(SmemU);   // ~73 KB
    cudaFuncSetAttribute(router_kernel,
                         cudaFuncAttributeMaxDynamicSharedMemorySize, smem);
    router_kernel<<<grid, NTHREADS, smem>>>(x, w, out, T);
}